// round 2
// baseline (speedup 1.0000x reference)
#include <cuda_runtime.h>
#include <math.h>

#define BB 4
#define VV 2048
#define TT 12
#define HH 64
#define EE 32768
#define VT (BB*VV)            /* 8192 */
#define TOTK 27
#define KK (TOTK*HH + HH)     /* 1792: 27*64 spline cols + 64 root cols */
#define NCONV 7

// ---------------- persistent device scratch (no runtime allocation) ----------------
__device__ float          g_Fv[VT * KK];          // 58.7 MB, L2-resident working set
__device__ float          g_Wp[NCONV * KK * HH];  // packed [Wk ; Wroot] per conv
__device__ float          g_basis[EE * 8];
__device__ unsigned short g_wis[EE * 8];          // wi * 64 (pre-scaled column offset)
__device__ int            g_deg[VV];
__device__ float          g_deginv[VV];
__device__ int            g_csroff[VV + 1];
__device__ int            g_csredge[EE];
__device__ float          g_h [VT * HH];
__device__ float          g_a [VT * HH];          // elu(conv5(h))
__device__ float          g_ho[VT * HH];          // h + tanh(conv6(a))
__device__ float          g_hr[VT * HH];
__device__ float          g_zh[VT * HH];
__device__ float          g_xg[3 * VT * HH];      // rx, zx, nx slices

// ---------------- weight packing: Wp[i][r][o] = r<1728 ? Wk[i][r][o] : Wroot[i][r-1728][o]
__global__ void k_pack(const float* __restrict__ Wk, const float* __restrict__ Wroot) {
    int idx = blockIdx.x * blockDim.x + threadIdx.x;
    if (idx >= NCONV * KK * HH) return;
    int o = idx % HH;
    int r = (idx / HH) % KK;
    int i = idx / (HH * KK);
    float v = (r < TOTK * HH) ? Wk[(i * TOTK * HH + r) * HH + o]
                              : Wroot[(i * HH + (r - TOTK * HH)) * HH + o];
    g_Wp[idx] = v;
}

// ---------------- degree-1 open B-spline basis + kernel indices + degree histogram
__global__ void k_basis(const float* __restrict__ attr, const int* __restrict__ eidx) {
    int e = blockIdx.x * blockDim.x + threadIdx.x;
    if (e >= EE) return;
    float fr[3]; int lo[3];
    #pragma unroll
    for (int d = 0; d < 3; d++) {
        float u  = attr[e * 3 + d] * 2.0f;       // * (K-1)
        float fl = floorf(u);
        fl = fminf(fmaxf(fl, 0.0f), 1.0f);       // clip to [0, K-2]
        fr[d] = u - fl;
        lo[d] = (int)fl;
    }
    atomicAdd(&g_deg[eidx[EE + e]], 1);
    #pragma unroll
    for (int s = 0; s < 8; s++) {
        int b0 = s & 1, b1 = (s >> 1) & 1, b2 = (s >> 2) & 1;
        float b = (b0 ? fr[0] : 1.0f - fr[0])
                * (b1 ? fr[1] : 1.0f - fr[1])
                * (b2 ? fr[2] : 1.0f - fr[2]);
        int w = (lo[0] + b0) + 3 * (lo[1] + b1) + 9 * (lo[2] + b2);
        g_basis[e * 8 + s] = b;
        g_wis  [e * 8 + s] = (unsigned short)(w * HH);
    }
}

// ---------------- exclusive scan of degrees (single block; one-time cost)
__global__ void k_scan() {
    __shared__ int sdeg[VV];
    __shared__ int soff[VV + 1];
    int tid = threadIdx.x;
    for (int v = tid; v < VV; v += blockDim.x) sdeg[v] = g_deg[v];
    __syncthreads();
    if (tid == 0) {
        int a = 0;
        for (int v = 0; v < VV; v++) { soff[v] = a; a += sdeg[v]; }
        soff[VV] = a;
    }
    __syncthreads();
    for (int v = tid; v < VV; v += blockDim.x) {
        g_csroff[v] = soff[v];
        g_deginv[v] = 1.0f / (float)max(sdeg[v], 1);
    }
    if (tid == 0) g_csroff[VV] = soff[VV];
}

// ---------------- stable CSR fill: one warp per dst node, ballot-ordered (deterministic)
__global__ void k_fill(const int* __restrict__ eidx) {
    int warp = (blockIdx.x * blockDim.x + threadIdx.x) >> 5;
    int lane = threadIdx.x & 31;
    if (warp >= VV) return;
    const int* dst = eidx + EE;
    int cnt = g_csroff[warp];
    for (int base = 0; base < EE; base += 32) {
        int d = dst[base + lane];
        unsigned m = __ballot_sync(0xFFFFFFFFu, d == warp);
        if (d == warp)
            g_csredge[cnt + __popc(m & ((1u << lane) - 1u))] = base + lane;
        cnt += __popc(m);
    }
}

// ---------------- scatter: build Fv rows (CSR gather, column-private smem accumulators)
__global__ void __launch_bounds__(256) k_scatter(const float* __restrict__ feat, int stride,
                                                 const int* __restrict__ eidx) {
    int c    = threadIdx.x;            // 0..63 : channel / Fv column owner
    int nsub = threadIdx.y;            // 0..3  : node sub-slot
    int node = blockIdx.x * 4 + nsub;  // 0..VT
    int b = node >> 11;                // / VV
    int v = node & (VV - 1);
    __shared__ float acc[4][TOTK * HH];
    float* ap = &acc[nsub][c];
    #pragma unroll
    for (int k = 0; k < TOTK; k++) ap[k * HH] = 0.0f;

    int i0 = g_csroff[v], i1 = g_csroff[v + 1];
    int base = b * VV;
    for (int ii = i0; ii < i1; ii++) {
        int e = g_csredge[ii];
        float4  bA = *(const float4*)&g_basis[e * 8];
        float4  bB = *(const float4*)&g_basis[e * 8 + 4];
        ushort4 wA = *(const ushort4*)&g_wis[e * 8];
        ushort4 wB = *(const ushort4*)&g_wis[e * 8 + 4];
        int src = eidx[e];
        float xs = feat[(base + src) * stride + c];
        ap[wA.x] += bA.x * xs;  ap[wA.y] += bA.y * xs;
        ap[wA.z] += bA.z * xs;  ap[wA.w] += bA.w * xs;
        ap[wB.x] += bB.x * xs;  ap[wB.y] += bB.y * xs;
        ap[wB.z] += bB.z * xs;  ap[wB.w] += bB.w * xs;
    }
    float di = g_deginv[v];
    float* o = &g_Fv[node * KK + c];
    #pragma unroll
    for (int k = 0; k < TOTK; k++) o[k * HH] = ap[k * HH] * di;  // deg_inv folded here
    o[TOTK * HH] = feat[node * stride + c];                       // root feature (unscaled)
}

// ---------------- GEMM: out[8192,64] = Fv[8192,1792] @ Wp[1792,64], fused epilogue
// EPI: 0 = +bias ; 1 = elu(+bias) ; 2 = extra + tanh(+bias)
template <int EPI>
__global__ void __launch_bounds__(256) k_gemm(const float* __restrict__ Wp,
                                              const float* __restrict__ bias,
                                              const float* __restrict__ extra,
                                              float* __restrict__ out) {
    __shared__ float As[2][16][68];   // +4 pad: 16B-aligned rows, reduced STS conflicts
    __shared__ float Bs[2][16][64];
    const int tid = threadIdx.x;
    const int tx = tid & 15, ty = tid >> 4;
    const int m0 = blockIdx.x * 64;
    const int ar  = tid >> 2;          // A-load row within tile (0..63)
    const int akq = (tid & 3) << 2;    // A-load k offset (0,4,8,12)
    const int br  = tid >> 4;          // B-load k row (0..15)
    const int bn  = (tid & 15) << 2;   // B-load n offset
    const float* Aap = &g_Fv[(m0 + ar) * KK + akq];

    float acc[4][4];
    #pragma unroll
    for (int i = 0; i < 4; i++)
        #pragma unroll
        for (int j = 0; j < 4; j++) acc[i][j] = 0.0f;

    {   // stage 0
        float4 va = *(const float4*)Aap;
        As[0][akq + 0][ar] = va.x; As[0][akq + 1][ar] = va.y;
        As[0][akq + 2][ar] = va.z; As[0][akq + 3][ar] = va.w;
        *(float4*)&Bs[0][br][bn] = *(const float4*)&Wp[br * HH + bn];
    }
    __syncthreads();

    const int NK = KK / 16;  // 112
    for (int s = 0; s < NK; s++) {
        int cur = s & 1, nxt = cur ^ 1;
        if (s + 1 < NK) {
            float4 va = *(const float4*)(Aap + (s + 1) * 16);
            As[nxt][akq + 0][ar] = va.x; As[nxt][akq + 1][ar] = va.y;
            As[nxt][akq + 2][ar] = va.z; As[nxt][akq + 3][ar] = va.w;
            *(float4*)&Bs[nxt][br][bn] = *(const float4*)&Wp[((s + 1) * 16 + br) * HH + bn];
        }
        #pragma unroll
        for (int kk = 0; kk < 16; kk++) {
            float a[4], b[4];
            *(float4*)a = *(const float4*)&As[cur][kk][ty << 2];
            *(float4*)b = *(const float4*)&Bs[cur][kk][tx << 2];
            #pragma unroll
            for (int i = 0; i < 4; i++)
                #pragma unroll
                for (int j = 0; j < 4; j++) acc[i][j] += a[i] * b[j];
        }
        __syncthreads();
    }

    #pragma unroll
    for (int i = 0; i < 4; i++) {
        int m = m0 + (ty << 2) + i;
        #pragma unroll
        for (int j = 0; j < 4; j++) {
            int n = (tx << 2) + j;
            float v = acc[i][j] + bias[n];
            if (EPI == 1)      v = (v > 0.0f) ? v : (expf(v) - 1.0f);
            else if (EPI == 2) v = extra[m * HH + n] + tanhf(v);
            out[m * HH + n] = v;
        }
    }
}

// ---------------- GRU gate fusion + output write
__global__ void k_gates(float* __restrict__ out, int t) {
    int i = blockIdx.x * blockDim.x + threadIdx.x;    // over VT*HH
    const int VH = VT * HH;
    float rx = g_xg[i], zx = g_xg[VH + i], nx = g_xg[2 * VH + i];
    float hr = g_hr[i], zh = g_zh[i],     ho = g_ho[i];
    float r = 1.0f / (1.0f + expf(-(rx + hr)));
    float z = 1.0f / (1.0f + expf(-(zx + zh)));
    float n = tanhf(nx + r * hr);
    float h = (1.0f - z) * n + z * ho;
    g_h[i] = h;
    int node = i >> 6, c = i & 63;
    out[(node * TT + t) * HH + c] = h;
}

// ---------------- launch ----------------
extern "C" void kernel_launch(void* const* d_in, const int* in_sizes, int n_in,
                              void* d_out, int out_size) {
    const float* x     = (const float*)d_in[0];
    const float* attr  = (const float*)d_in[1];
    const float* Wk    = (const float*)d_in[2];
    const float* Wroot = (const float*)d_in[3];
    const float* bias  = (const float*)d_in[4];
    const int*   eidx  = (const int*)d_in[5];
    float*       out   = (float*)d_out;

    float *pWp, *pH, *pA, *pHO, *pHR, *pZH, *pXG;
    int   *pDeg;
    cudaGetSymbolAddress((void**)&pWp,  g_Wp);
    cudaGetSymbolAddress((void**)&pH,   g_h);
    cudaGetSymbolAddress((void**)&pA,   g_a);
    cudaGetSymbolAddress((void**)&pHO,  g_ho);
    cudaGetSymbolAddress((void**)&pHR,  g_hr);
    cudaGetSymbolAddress((void**)&pZH,  g_zh);
    cudaGetSymbolAddress((void**)&pXG,  g_xg);
    cudaGetSymbolAddress((void**)&pDeg, g_deg);

    cudaMemsetAsync(pDeg, 0, VV * sizeof(int));
    cudaMemsetAsync(pH,   0, VT * HH * sizeof(float));

    k_pack <<<(NCONV * KK * HH + 255) / 256, 256>>>(Wk, Wroot);
    k_basis<<<EE / 256, 256>>>(attr, eidx);
    k_scan <<<1, 1024>>>();
    k_fill <<<VV / 8, 256>>>(eidx);

    const dim3 sblk(64, 4);
    const int  GG = VT / 64;      // GEMM grid (128)
    const int  VH = VT * HH;

    for (int t = 0; t < TT; t++) {
        // ODE: a = elu(conv5(h)) ; ho = h + tanh(conv6(a))
        k_scatter<<<VT / 4, sblk>>>(pH, HH, eidx);
        k_gemm<1><<<GG, 256>>>(pWp + 5 * KK * HH, bias + 5 * HH, nullptr, pA);
        k_scatter<<<VT / 4, sblk>>>(pA, HH, eidx);
        k_gemm<2><<<GG, 256>>>(pWp + 6 * KK * HH, bias + 6 * HH, pH, pHO);
        // GRU h-side: hr = conv1(ho), zh = conv3(ho)
        k_scatter<<<VT / 4, sblk>>>(pHO, HH, eidx);
        k_gemm<0><<<GG, 256>>>(pWp + 1 * KK * HH, bias + 1 * HH, nullptr, pHR);
        k_gemm<0><<<GG, 256>>>(pWp + 3 * KK * HH, bias + 3 * HH, nullptr, pZH);
        // GRU x-side: rx = conv0(xt), zx = conv2(xt), nx = conv4(xt)
        k_scatter<<<VT / 4, sblk>>>(x + t * HH, TT * HH, eidx);
        k_gemm<0><<<GG, 256>>>(pWp + 0 * KK * HH, bias + 0 * HH, nullptr, pXG);
        k_gemm<0><<<GG, 256>>>(pWp + 2 * KK * HH, bias + 2 * HH, nullptr, pXG + VH);
        k_gemm<0><<<GG, 256>>>(pWp + 4 * KK * HH, bias + 4 * HH, nullptr, pXG + 2 * VH);
        // gates + output
        k_gates<<<VH / 256, 256>>>(out, t);
    }
}

// round 4
// speedup vs baseline: 1.9019x; 1.9019x over previous
#include <cuda_runtime.h>
#include <cstdint>
#include <math.h>

#define BB 4
#define VV 2048
#define TT 12
#define HH 64
#define EE 32768
#define VT (BB*VV)            /* 8192 */
#define TOTK 27
#define KK (TOTK*HH + HH)     /* 1792 */
#define NCONV 7
#define VH (VT*HH)

// ================= helpers =================
__device__ __forceinline__ uint32_t smem_u32(const void* p) {
    uint32_t a;
    asm("{ .reg .u64 t; cvta.to.shared.u64 t, %1; cvt.u32.u64 %0, t; }" : "=r"(a) : "l"(p));
    return a;
}
__device__ __forceinline__ void cp16(uint32_t dst, const void* src) {
    asm volatile("cp.async.ca.shared.global [%0], [%1], 16;" :: "r"(dst), "l"(src));
}
#define CP_COMMIT() asm volatile("cp.async.commit_group;" ::: "memory")
#define CP_WAIT1()  asm volatile("cp.async.wait_group 1;" ::: "memory")
#define CP_WAIT0()  asm volatile("cp.async.wait_group 0;" ::: "memory")

__device__ __forceinline__ float to_tf32(float v) {
    uint32_t r;
    asm("cvt.rna.tf32.f32 %0, %1;" : "=r"(r) : "f"(v));
    return __uint_as_float(r);
}

// ================= persistent device scratch =================
__device__ __align__(256) float          g_Fv[VT * KK];          // 58.7 MB (tf32-rounded)
__device__ __align__(256) float          g_Wt[NCONV * HH * KK];  // [perm conv][n][k], tf32-rounded
__device__ __align__(256) float          g_biasP[NCONV * HH];
__device__ __align__(256) float          g_basis[EE * 8];
__device__ __align__(256) unsigned short g_wis[EE * 8];
__device__ int            g_deg[VV];
__device__ float          g_deginv[VV];
__device__ int            g_csroff[VV + 1];
__device__ int            g_csredge[EE];
__device__ __align__(256) float g_h [VH];
__device__ __align__(256) float g_a [VH];
__device__ __align__(256) float g_ho[VH];
__device__ __align__(256) float g_hz[2 * VH];    // hr, zh
__device__ __align__(256) float g_xg[3 * VH];    // rx, zx, nx

// ---------------- weight pack: transpose + conv permutation {0,2,4,1,3,5,6}, tf32 round ----
__global__ void k_pack(const float* __restrict__ Wk, const float* __restrict__ Wroot,
                       const float* __restrict__ bias) {
    int idx = blockIdx.x * blockDim.x + threadIdx.x;
    if (idx >= NCONV * HH * KK) return;
    int k = idx % KK;
    int n = (idx / KK) & 63;
    int p = idx / (KK * HH);
    const int perm[7] = {0, 2, 4, 1, 3, 5, 6};
    int conv = perm[p];
    float v = (k < TOTK * HH) ? Wk[(conv * TOTK * HH + k) * HH + n]
                              : Wroot[(conv * HH + (k - TOTK * HH)) * HH + n];
    g_Wt[idx] = to_tf32(v);
    if (k == 0) g_biasP[p * HH + n] = bias[conv * HH + n];
}

// ---------------- spline basis + degree histogram ----------------
__global__ void k_basis(const float* __restrict__ attr, const int* __restrict__ eidx) {
    int e = blockIdx.x * blockDim.x + threadIdx.x;
    if (e >= EE) return;
    float fr[3]; int lo[3];
    #pragma unroll
    for (int d = 0; d < 3; d++) {
        float u  = attr[e * 3 + d] * 2.0f;
        float fl = fminf(fmaxf(floorf(u), 0.0f), 1.0f);
        fr[d] = u - fl;
        lo[d] = (int)fl;
    }
    atomicAdd(&g_deg[eidx[EE + e]], 1);
    #pragma unroll
    for (int s = 0; s < 8; s++) {
        int b0 = s & 1, b1 = (s >> 1) & 1, b2 = (s >> 2) & 1;
        float b = (b0 ? fr[0] : 1.0f - fr[0])
                * (b1 ? fr[1] : 1.0f - fr[1])
                * (b2 ? fr[2] : 1.0f - fr[2]);
        int w = (lo[0] + b0) + 3 * (lo[1] + b1) + 9 * (lo[2] + b2);
        g_basis[e * 8 + s] = b;
        g_wis  [e * 8 + s] = (unsigned short)(w * HH);
    }
}

__global__ void k_scan() {
    __shared__ int sdeg[VV];
    __shared__ int soff[VV + 1];
    int tid = threadIdx.x;
    for (int v = tid; v < VV; v += blockDim.x) sdeg[v] = g_deg[v];
    __syncthreads();
    if (tid == 0) {
        int a = 0;
        for (int v = 0; v < VV; v++) { soff[v] = a; a += sdeg[v]; }
        soff[VV] = a;
    }
    __syncthreads();
    for (int v = tid; v < VV; v += blockDim.x) {
        g_csroff[v] = soff[v];
        g_deginv[v] = 1.0f / (float)max(sdeg[v], 1);
    }
    if (tid == 0) g_csroff[VV] = soff[VV];
}

__global__ void k_fill(const int* __restrict__ eidx) {
    int warp = (blockIdx.x * blockDim.x + threadIdx.x) >> 5;
    int lane = threadIdx.x & 31;
    if (warp >= VV) return;
    const int* dst = eidx + EE;
    int cnt = g_csroff[warp];
    for (int base = 0; base < EE; base += 32) {
        int d = dst[base + lane];
        unsigned m = __ballot_sync(0xFFFFFFFFu, d == warp);
        if (d == warp)
            g_csredge[cnt + __popc(m & ((1u << lane) - 1u))] = base + lane;
        cnt += __popc(m);
    }
}

// ---------------- scatter: Fv rows via CSR gather (column-private smem), tf32-rounded out ----
__global__ void __launch_bounds__(256) k_scatter(const float* __restrict__ feat, int stride,
                                                 const int* __restrict__ eidx) {
    int c    = threadIdx.x;
    int nsub = threadIdx.y;
    int node = blockIdx.x * 4 + nsub;
    int b = node >> 11;
    int v = node & (VV - 1);
    __shared__ float acc[4][TOTK * HH];
    float* ap = &acc[nsub][c];
    #pragma unroll
    for (int k = 0; k < TOTK; k++) ap[k * HH] = 0.0f;

    int i0 = g_csroff[v], i1 = g_csroff[v + 1];
    int base = b * VV;
    for (int ii = i0; ii < i1; ii++) {
        int e = g_csredge[ii];
        float4  bA = *(const float4*)&g_basis[e * 8];
        float4  bB = *(const float4*)&g_basis[e * 8 + 4];
        ushort4 wA = *(const ushort4*)&g_wis[e * 8];
        ushort4 wB = *(const ushort4*)&g_wis[e * 8 + 4];
        int src = eidx[e];
        float xs = feat[(base + src) * stride + c];
        ap[wA.x] += bA.x * xs;  ap[wA.y] += bA.y * xs;
        ap[wA.z] += bA.z * xs;  ap[wA.w] += bA.w * xs;
        ap[wB.x] += bB.x * xs;  ap[wB.y] += bB.y * xs;
        ap[wB.z] += bB.z * xs;  ap[wB.w] += bB.w * xs;
    }
    float di = g_deginv[v];
    float* o = &g_Fv[node * KK + c];
    #pragma unroll
    for (int k = 0; k < TOTK; k++) o[k * HH] = to_tf32(ap[k * HH] * di);
    o[TOTK * HH] = to_tf32(feat[node * stride + c]);
}

// ---------------- TF32 mma.sync GEMM: out = Fv[8192,1792] @ Wt^T ----------------
// Block: 64(M) x 64(N) x K=1792 ; 128 threads = 4 warps (2x2), warp tile 32x32.
// gridDim.y picks the conv within the packed group (Bw/bias/out offset by y).
// EPI: 0 plain(+bias), 1 elu(+bias), 2 extra + tanh(+bias).
template <int EPI>
__global__ void __launch_bounds__(128) k_gemm(const float* __restrict__ Bw,
                                              const float* __restrict__ bias,
                                              const float* __restrict__ extra,
                                              float* __restrict__ out) {
    __shared__ __align__(16) float As[2][64][36];  // pitch 36: frag LDS conflict-free
    __shared__ __align__(16) float Bs[2][64][36];

    const int tid  = threadIdx.x;
    const int m0   = blockIdx.x * 64;
    const int grp  = blockIdx.y;
    Bw   += grp * 64 * KK;
    bias += grp * 64;
    out  += grp * VH;

    const int lane = tid & 31, wid = tid >> 5;
    const int wm = (wid & 1) * 32, wn = (wid >> 1) * 32;
    const int g  = lane >> 2,  tq = lane & 3;

    float c[2][4][4];
    #pragma unroll
    for (int mt = 0; mt < 2; mt++)
        #pragma unroll
        for (int nt = 0; nt < 4; nt++)
            #pragma unroll
            for (int i = 0; i < 4; i++) c[mt][nt][i] = 0.0f;

    // tile loaders: 64 rows x 32 floats, 2 threads/row, 4 x 16B per thread
    const int arow = tid >> 1;
    const int as0  = (tid & 1) * 4;
    const float* Ag = &g_Fv[(uint64_t)(m0 + arow) * KK];
    const float* Bg = &Bw[(uint64_t)arow * KK];
    const uint32_t sA = smem_u32(&As[0][0][0]);
    const uint32_t sB = smem_u32(&Bs[0][0][0]);

    auto load_tiles = [&](int kc, int buf) {
        uint32_t da = sA + (uint32_t)buf * (64 * 36 * 4) + (uint32_t)arow * 144;
        uint32_t db = sB + (uint32_t)buf * (64 * 36 * 4) + (uint32_t)arow * 144;
        const float* ga = Ag + kc * 32;
        const float* gb = Bg + kc * 32;
        #pragma unroll
        for (int i = 0; i < 4; i++) {
            int s = as0 + i;
            cp16(da + s * 16, ga + s * 4);
            cp16(db + s * 16, gb + s * 4);
        }
    };

    load_tiles(0, 0);
    CP_COMMIT();

    const int NCH = KK / 32;   // 56
    for (int ck = 0; ck < NCH; ck++) {
        if (ck + 1 < NCH) { load_tiles(ck + 1, (ck + 1) & 1); CP_COMMIT(); CP_WAIT1(); }
        else              { CP_WAIT0(); }
        __syncthreads();
        const int buf = ck & 1;
        #pragma unroll
        for (int s8 = 0; s8 < 4; s8++) {
            const int k8 = s8 * 8;
            uint32_t a[2][4], b[4][2];
            #pragma unroll
            for (int mt = 0; mt < 2; mt++) {
                int r0 = wm + mt * 16 + g;
                a[mt][0] = __float_as_uint(As[buf][r0    ][k8 + tq]);
                a[mt][1] = __float_as_uint(As[buf][r0 + 8][k8 + tq]);
                a[mt][2] = __float_as_uint(As[buf][r0    ][k8 + tq + 4]);
                a[mt][3] = __float_as_uint(As[buf][r0 + 8][k8 + tq + 4]);
            }
            #pragma unroll
            for (int nt = 0; nt < 4; nt++) {
                int br = wn + nt * 8 + g;
                b[nt][0] = __float_as_uint(Bs[buf][br][k8 + tq]);
                b[nt][1] = __float_as_uint(Bs[buf][br][k8 + tq + 4]);
            }
            #pragma unroll
            for (int mt = 0; mt < 2; mt++)
                #pragma unroll
                for (int nt = 0; nt < 4; nt++) {
                    float* cc = c[mt][nt];
                    asm volatile(
                        "mma.sync.aligned.m16n8k8.row.col.f32.tf32.tf32.f32 "
                        "{%0,%1,%2,%3},{%4,%5,%6,%7},{%8,%9},{%0,%1,%2,%3};"
                        : "+f"(cc[0]), "+f"(cc[1]), "+f"(cc[2]), "+f"(cc[3])
                        : "r"(a[mt][0]), "r"(a[mt][1]), "r"(a[mt][2]), "r"(a[mt][3]),
                          "r"(b[nt][0]), "r"(b[nt][1]));
                }
        }
        __syncthreads();
    }

    // epilogue: bias + activation (+extra), float2 stores
    #pragma unroll
    for (int mt = 0; mt < 2; mt++) {
        #pragma unroll
        for (int nt = 0; nt < 4; nt++) {
            int col = wn + nt * 8 + 2 * tq;
            float b0 = bias[col], b1 = bias[col + 1];
            #pragma unroll
            for (int half = 0; half < 2; half++) {
                int row = m0 + wm + mt * 16 + g + half * 8;
                float v0 = c[mt][nt][half * 2 + 0] + b0;
                float v1 = c[mt][nt][half * 2 + 1] + b1;
                if (EPI == 1) {
                    v0 = (v0 > 0.0f) ? v0 : (expf(v0) - 1.0f);
                    v1 = (v1 > 0.0f) ? v1 : (expf(v1) - 1.0f);
                }
                int o = row * 64 + col;
                if (EPI == 2) {
                    float2 e2 = *(const float2*)&extra[o];
                    v0 = e2.x + tanhf(v0);
                    v1 = e2.y + tanhf(v1);
                }
                float2 st = make_float2(v0, v1);
                *(float2*)&out[o] = st;
            }
        }
    }
}

// ---------------- GRU gates + output ----------------
__global__ void k_gates(float* __restrict__ out, int t) {
    int i = blockIdx.x * blockDim.x + threadIdx.x;
    float rx = g_xg[i], zx = g_xg[VH + i], nx = g_xg[2 * VH + i];
    float hr = g_hz[i], zh = g_hz[VH + i], ho = g_ho[i];
    float r = 1.0f / (1.0f + expf(-(rx + hr)));
    float z = 1.0f / (1.0f + expf(-(zx + zh)));
    float n = tanhf(nx + r * hr);
    float h = (1.0f - z) * n + z * ho;
    g_h[i] = h;
    int node = i >> 6, c = i & 63;
    out[(node * TT + t) * HH + c] = h;
}

// ---------------- launch ----------------
extern "C" void kernel_launch(void* const* d_in, const int* in_sizes, int n_in,
                              void* d_out, int out_size) {
    const float* x     = (const float*)d_in[0];
    const float* attr  = (const float*)d_in[1];
    const float* Wk    = (const float*)d_in[2];
    const float* Wroot = (const float*)d_in[3];
    const float* bias  = (const float*)d_in[4];
    const int*   eidx  = (const int*)d_in[5];
    float*       out   = (float*)d_out;

    float *pWt, *pBias, *pH, *pA, *pHO, *pHZ, *pXG;
    int   *pDeg;
    cudaGetSymbolAddress((void**)&pWt,   g_Wt);
    cudaGetSymbolAddress((void**)&pBias, g_biasP);
    cudaGetSymbolAddress((void**)&pH,    g_h);
    cudaGetSymbolAddress((void**)&pA,    g_a);
    cudaGetSymbolAddress((void**)&pHO,   g_ho);
    cudaGetSymbolAddress((void**)&pHZ,   g_hz);
    cudaGetSymbolAddress((void**)&pXG,   g_xg);
    cudaGetSymbolAddress((void**)&pDeg,  g_deg);

    cudaMemsetAsync(pDeg, 0, VV * sizeof(int));
    cudaMemsetAsync(pH,   0, VH * sizeof(float));

    k_pack <<<(NCONV * HH * KK + 255) / 256, 256>>>(Wk, Wroot, bias);
    k_basis<<<EE / 256, 256>>>(attr, eidx);
    k_scan <<<1, 1024>>>();
    k_fill <<<VV / 8, 256>>>(eidx);

    const dim3 sblk(64, 4);
    const int  HK = HH * KK;
    const dim3 g1(VT / 64, 1), g2(VT / 64, 2), g3(VT / 64, 3);

    for (int t = 0; t < TT; t++) {
        // ODE: a = elu(conv5(h)) ; ho = h + tanh(conv6(a))
        k_scatter<<<VT / 4, sblk>>>(pH, HH, eidx);
        k_gemm<1><<<g1, 128>>>(pWt + 5 * HK, pBias + 5 * HH, nullptr, pA);
        k_scatter<<<VT / 4, sblk>>>(pA, HH, eidx);
        k_gemm<2><<<g1, 128>>>(pWt + 6 * HK, pBias + 6 * HH, pH, pHO);
        // GRU h-side fused: [hr | zh] = conv{1,3}(ho)
        k_scatter<<<VT / 4, sblk>>>(pHO, HH, eidx);
        k_gemm<0><<<g2, 128>>>(pWt + 3 * HK, pBias + 3 * HH, nullptr, pHZ);
        // GRU x-side fused: [rx | zx | nx] = conv{0,2,4}(x_t)
        k_scatter<<<VT / 4, sblk>>>(x + t * HH, TT * HH, eidx);
        k_gemm<0><<<g3, 128>>>(pWt, pBias, nullptr, pXG);
        // gates + output
        k_gates<<<VH / 256, 256>>>(out, t);
    }
}